// round 4
// baseline (speedup 1.0000x reference)
#include <cuda_runtime.h>
#include <math.h>

// SlowMAF: 31 stacked per-dim MLPs (32 -> 24 -> 24 -> 24 -> 2, LeakyReLU 0.2),
// z[:, 31-i] = x[:,i]*exp(s_i)+t_i, log_det = sum_i s_i.
// fp32x2 packed (output-neuron pairs), 1 row/thread, LDS.128 weight loads,
// 6 CTAs/SM occupancy target.
// Inputs (metadata order): x, p0, W1, b1, W2, b2, W3, b3, W4, b4
// Output: [ z (B*32 f32), log_det (B f32) ]

#define NHID 24
#define NP   (NHID / 2)      // 12 packed output pairs
#define THREADS 128
#define ROWS_PER_CTA 128     // 1 row per thread
#define XPITCH 33

typedef unsigned long long u64;
typedef unsigned int u32;

__device__ __forceinline__ u64 pack2(float lo, float hi) {
    u64 r; asm("mov.b64 %0, {%1, %2};" : "=l"(r) : "f"(lo), "f"(hi)); return r;
}
__device__ __forceinline__ void unpack2(float& lo, float& hi, u64 v) {
    asm("mov.b64 {%0, %1}, %2;" : "=f"(lo), "=f"(hi) : "l"(v));
}
__device__ __forceinline__ u64 fma2(u64 a, u64 b, u64 c) {
    u64 d; asm("fma.rn.f32x2 %0, %1, %2, %3;" : "=l"(d) : "l"(a), "l"(b), "l"(c)); return d;
}
__device__ __forceinline__ u64 mul2(u64 a, u64 b) {
    u64 d; asm("mul.rn.f32x2 %0, %1, %2;" : "=l"(d) : "l"(a), "l"(b)); return d;
}
// lrelu(a) = max(a, 0.2a) = 0.6a + 0.4|a| lanewise.
__device__ __forceinline__ u64 lrelu2(u64 a) {
    const u64 C06 = 0x3F19999A3F19999Aull;  // {0.6f, 0.6f}
    const u64 C04 = 0x3ECCCCCD3ECCCCCDull;  // {0.4f, 0.4f}
    u64 absa = a & 0x7FFFFFFF7FFFFFFFull;
    return fma2(absa, C04, mul2(a, C06));
}
// 16B shared load -> two packed u64 (explicit v4 to guarantee LDS.128)
__device__ __forceinline__ void lds128_pair(const float* p, u64& w0, u64& w1) {
    u32 a, b, c, d;
    asm volatile("ld.shared.v4.b32 {%0, %1, %2, %3}, [%4];"
                 : "=r"(a), "=r"(b), "=r"(c), "=r"(d)
                 : "l"((unsigned long long)__cvta_generic_to_shared(p)));
    asm("mov.b64 %0, {%1, %2};" : "=l"(w0) : "r"(a), "r"(b));
    asm("mov.b64 %0, {%1, %2};" : "=l"(w1) : "r"(c), "r"(d));
}

__global__ void slowmaf_init_kernel(const float* __restrict__ x,
                                    const float* __restrict__ p0,
                                    float* __restrict__ z,
                                    float* __restrict__ ld, int B) {
    int row = blockIdx.x * blockDim.x + threadIdx.x;
    if (row < B) {
        float s0 = p0[0], t0 = p0[1];
        z[row * 32 + 31] = x[row * 32 + 0] * expf(s0) + t0;  // order[0] = 31
        ld[row] = s0;
    }
}

__global__ __launch_bounds__(THREADS, 6) void slowmaf_main_kernel(
    const float* __restrict__ x,
    const float* __restrict__ W1, const float* __restrict__ b1,
    const float* __restrict__ W2, const float* __restrict__ b2,
    const float* __restrict__ W3, const float* __restrict__ b3,
    const float* __restrict__ W4, const float* __restrict__ b4,
    float* __restrict__ z, float* __restrict__ ld)
{
    __shared__ float xs[ROWS_PER_CTA * XPITCH];
    __shared__ __align__(16) float w1t[32 * NHID];     // [j][o]
    __shared__ __align__(16) float w2t[NHID * NHID];   // [hin][o]
    __shared__ __align__(16) float w3t[NHID * NHID];   // [hin][o]
    __shared__ __align__(16) float w4sv[NHID];         // ws[hin]
    __shared__ __align__(16) float w4tv[NHID];         // wt[hin]
    __shared__ __align__(16) float b1s[NHID], b2s[NHID], b3s[NHID];
    __shared__ float b4s[2];

    const int k    = blockIdx.y;               // 0..30 (torch layer i = k+1)
    const int tile = blockIdx.x * ROWS_PER_CTA;
    const int tid  = threadIdx.x;

    // --- stage x tile (coalesced) ---
    #pragma unroll
    for (int it = 0; it < 32; it++) {
        int idx = it * THREADS + tid;
        int r = idx >> 5, c = idx & 31;
        xs[r * XPITCH + c] = x[(tile + r) * 32 + c];
    }
    // --- stage weights transposed (o contiguous, rows 96B, 16B aligned) ---
    for (int idx = tid; idx < 32 * NHID; idx += THREADS) {
        int j = idx / NHID, o = idx % NHID;
        w1t[idx] = W1[k * (NHID * 32) + o * 32 + j];
    }
    for (int idx = tid; idx < NHID * NHID; idx += THREADS) {
        int hin = idx / NHID, o = idx % NHID;
        w2t[idx] = W2[k * (NHID * NHID) + o * NHID + hin];
        w3t[idx] = W3[k * (NHID * NHID) + o * NHID + hin];
    }
    if (tid < 2 * NHID) {
        // W4[k, o, hin]: row o=0 is ws, o=1 is wt, both contiguous
        float v = W4[k * (2 * NHID) + tid];
        if (tid < NHID) w4sv[tid] = v; else w4tv[tid - NHID] = v;
    }
    if (tid < NHID) {
        b1s[tid] = b1[k * NHID + tid];
        b2s[tid] = b2[k * NHID + tid];
        b3s[tid] = b3[k * NHID + tid];
    }
    if (tid < 2) b4s[tid] = b4[k * 2 + tid];
    __syncthreads();

    u64 A[NP], H[NP];
    const float* xp = &xs[tid * XPITCH];
    const u64* b1p = (const u64*)b1s;
    const u64* b2p = (const u64*)b2s;
    const u64* b3p = (const u64*)b3s;

    // ---- layer 1 (causal: columns 0..k) ----
    #pragma unroll
    for (int o = 0; o < NP; o++) A[o] = b1p[o];
    for (int j = 0; j <= k; j++) {
        float xv = xp[j];
        u64 v = pack2(xv, xv);
        const float* wrow = &w1t[j * NHID];
        #pragma unroll
        for (int o2 = 0; o2 < NP / 2; o2++) {
            u64 w0, w1;
            lds128_pair(wrow + 4 * o2, w0, w1);
            A[2 * o2]     = fma2(w0, v, A[2 * o2]);
            A[2 * o2 + 1] = fma2(w1, v, A[2 * o2 + 1]);
        }
    }
    #pragma unroll
    for (int o = 0; o < NP; o++) H[o] = lrelu2(A[o]);

    // ---- layer 2 ----
    #pragma unroll
    for (int o = 0; o < NP; o++) A[o] = b2p[o];
    #pragma unroll
    for (int hp = 0; hp < NP; hp++) {
        float hlo, hhi;
        unpack2(hlo, hhi, H[hp]);
        u64 va = pack2(hlo, hlo), vb = pack2(hhi, hhi);
        const float* rowa = &w2t[(2 * hp) * NHID];
        const float* rowb = &w2t[(2 * hp + 1) * NHID];
        #pragma unroll
        for (int o2 = 0; o2 < NP / 2; o2++) {
            u64 wa0, wa1, wb0, wb1;
            lds128_pair(rowa + 4 * o2, wa0, wa1);
            lds128_pair(rowb + 4 * o2, wb0, wb1);
            A[2 * o2]     = fma2(wa0, va, A[2 * o2]);
            A[2 * o2 + 1] = fma2(wa1, va, A[2 * o2 + 1]);
            A[2 * o2]     = fma2(wb0, vb, A[2 * o2]);
            A[2 * o2 + 1] = fma2(wb1, vb, A[2 * o2 + 1]);
        }
    }
    #pragma unroll
    for (int o = 0; o < NP; o++) H[o] = lrelu2(A[o]);

    // ---- layer 3 ----
    #pragma unroll
    for (int o = 0; o < NP; o++) A[o] = b3p[o];
    #pragma unroll
    for (int hp = 0; hp < NP; hp++) {
        float hlo, hhi;
        unpack2(hlo, hhi, H[hp]);
        u64 va = pack2(hlo, hlo), vb = pack2(hhi, hhi);
        const float* rowa = &w3t[(2 * hp) * NHID];
        const float* rowb = &w3t[(2 * hp + 1) * NHID];
        #pragma unroll
        for (int o2 = 0; o2 < NP / 2; o2++) {
            u64 wa0, wa1, wb0, wb1;
            lds128_pair(rowa + 4 * o2, wa0, wa1);
            lds128_pair(rowb + 4 * o2, wb0, wb1);
            A[2 * o2]     = fma2(wa0, va, A[2 * o2]);
            A[2 * o2 + 1] = fma2(wa1, va, A[2 * o2 + 1]);
            A[2 * o2]     = fma2(wb0, vb, A[2 * o2]);
            A[2 * o2 + 1] = fma2(wb1, vb, A[2 * o2 + 1]);
        }
    }
    #pragma unroll
    for (int o = 0; o < NP; o++) H[o] = lrelu2(A[o]);

    // ---- layer 4: packed dot products (lanes hold even/odd partial sums) ----
    const u64* wsp = (const u64*)w4sv;
    const u64* wtp = (const u64*)w4tv;
    u64 sacc = 0, tacc = 0;
    #pragma unroll
    for (int hp = 0; hp < NP; hp++) {
        sacc = fma2(wsp[hp], H[hp], sacc);
        tacc = fma2(wtp[hp], H[hp], tacc);
    }
    float se, so, te, to;
    unpack2(se, so, sacc);
    unpack2(te, to, tacc);
    float s = b4s[0] + se + so;
    float t = b4s[1] + te + to;

    // ---- epilogue: z[:, 30-k] = x[:,k+1]*exp(s)+t ; logdet += s ----
    const int col = 30 - k;
    const int row = tile + tid;
    z[row * 32 + col] = xp[k + 1] * expf(s) + t;
    atomicAdd(&ld[row], s);
}

extern "C" void kernel_launch(void* const* d_in, const int* in_sizes, int n_in,
                              void* d_out, int out_size) {
    const float* x  = (const float*)d_in[0];
    const float* p0 = (const float*)d_in[1];
    const float* W1 = (const float*)d_in[2];
    const float* b1 = (const float*)d_in[3];
    const float* W2 = (const float*)d_in[4];
    const float* b2 = (const float*)d_in[5];
    const float* W3 = (const float*)d_in[6];
    const float* b3 = (const float*)d_in[7];
    const float* W4 = (const float*)d_in[8];
    const float* b4 = (const float*)d_in[9];

    const int B = in_sizes[0] / 32;          // 65536
    float* z  = (float*)d_out;               // B*32
    float* ld = z + (size_t)B * 32;          // B

    slowmaf_init_kernel<<<(B + 255) / 256, 256>>>(x, p0, z, ld, B);

    dim3 grid(B / ROWS_PER_CTA, 31);
    slowmaf_main_kernel<<<grid, THREADS>>>(x, W1, b1, W2, b2, W3, b3, W4, b4, z, ld);
}

// round 5
// speedup vs baseline: 1.2809x; 1.2809x over previous
#include <cuda_runtime.h>
#include <math.h>

// SlowMAF: 31 stacked per-dim MLPs (32 -> 24 -> 24 -> 24 -> 2, LeakyReLU 0.2),
// z[:, 31-i] = x[:,i]*exp(s_i)+t_i, log_det = sum_i s_i.
// fp32x2 packed output pairs, 2 rows/thread (amortize weight LDS),
// LDS.128 weight loads (best LDS:FMA ratio).
// Inputs (metadata order): x, p0, W1, b1, W2, b2, W3, b3, W4, b4
// Output: [ z (B*32 f32), log_det (B f32) ]

#define NHID 24
#define NP   (NHID / 2)      // 12 packed output pairs
#define THREADS 128
#define ROWS_PER_CTA 256     // 2 rows per thread
#define XPITCH 33

typedef unsigned long long u64;
typedef unsigned int u32;

__device__ __forceinline__ u64 pack2(float lo, float hi) {
    u64 r; asm("mov.b64 %0, {%1, %2};" : "=l"(r) : "f"(lo), "f"(hi)); return r;
}
__device__ __forceinline__ void unpack2(float& lo, float& hi, u64 v) {
    asm("mov.b64 {%0, %1}, %2;" : "=f"(lo), "=f"(hi) : "l"(v));
}
__device__ __forceinline__ u64 fma2(u64 a, u64 b, u64 c) {
    u64 d; asm("fma.rn.f32x2 %0, %1, %2, %3;" : "=l"(d) : "l"(a), "l"(b), "l"(c)); return d;
}
__device__ __forceinline__ u64 mul2(u64 a, u64 b) {
    u64 d; asm("mul.rn.f32x2 %0, %1, %2;" : "=l"(d) : "l"(a), "l"(b)); return d;
}
// lrelu(a) = max(a, 0.2a) = 0.6a + 0.4|a| lanewise.
__device__ __forceinline__ u64 lrelu2(u64 a) {
    const u64 C06 = 0x3F19999A3F19999Aull;  // {0.6f, 0.6f}
    const u64 C04 = 0x3ECCCCCD3ECCCCCDull;  // {0.4f, 0.4f}
    u64 absa = a & 0x7FFFFFFF7FFFFFFFull;
    return fma2(absa, C04, mul2(a, C06));
}
// 16B shared load -> two packed u64 (guaranteed LDS.128)
__device__ __forceinline__ void lds128_pair(const float* p, u64& w0, u64& w1) {
    u32 a, b, c, d;
    asm volatile("ld.shared.v4.b32 {%0, %1, %2, %3}, [%4];"
                 : "=r"(a), "=r"(b), "=r"(c), "=r"(d)
                 : "l"((unsigned long long)__cvta_generic_to_shared(p)));
    asm("mov.b64 %0, {%1, %2};" : "=l"(w0) : "r"(a), "r"(b));
    asm("mov.b64 %0, {%1, %2};" : "=l"(w1) : "r"(c), "r"(d));
}

__global__ void slowmaf_init_kernel(const float* __restrict__ x,
                                    const float* __restrict__ p0,
                                    float* __restrict__ z,
                                    float* __restrict__ ld, int B) {
    int row = blockIdx.x * blockDim.x + threadIdx.x;
    if (row < B) {
        float s0 = p0[0], t0 = p0[1];
        z[row * 32 + 31] = x[row * 32 + 0] * expf(s0) + t0;  // order[0] = 31
        ld[row] = s0;
    }
}

__global__ __launch_bounds__(THREADS, 4) void slowmaf_main_kernel(
    const float* __restrict__ x,
    const float* __restrict__ W1, const float* __restrict__ b1,
    const float* __restrict__ W2, const float* __restrict__ b2,
    const float* __restrict__ W3, const float* __restrict__ b3,
    const float* __restrict__ W4, const float* __restrict__ b4,
    float* __restrict__ z, float* __restrict__ ld)
{
    __shared__ float xs[ROWS_PER_CTA * XPITCH];
    __shared__ __align__(16) float w1t[32 * NHID];     // [j][o]
    __shared__ __align__(16) float w2t[NHID * NHID];   // [hin][o]
    __shared__ __align__(16) float w3t[NHID * NHID];   // [hin][o]
    __shared__ __align__(16) float w4sv[NHID];         // ws[hin]
    __shared__ __align__(16) float w4tv[NHID];         // wt[hin]
    __shared__ __align__(16) float b1s[NHID], b2s[NHID], b3s[NHID];
    __shared__ float b4s[2];

    const int k    = blockIdx.y;               // 0..30 (torch layer i = k+1)
    const int tile = blockIdx.x * ROWS_PER_CTA;
    const int tid  = threadIdx.x;

    // --- stage x tile (coalesced) ---
    #pragma unroll 4
    for (int idx = tid; idx < ROWS_PER_CTA * 32; idx += THREADS) {
        int r = idx >> 5, c = idx & 31;
        xs[r * XPITCH + c] = x[(tile + r) * 32 + c];
    }
    // --- stage weights transposed (o contiguous; rows 96B = 16B aligned) ---
    for (int idx = tid; idx < 32 * NHID; idx += THREADS) {
        int j = idx / NHID, o = idx % NHID;
        w1t[idx] = W1[k * (NHID * 32) + o * 32 + j];
    }
    for (int idx = tid; idx < NHID * NHID; idx += THREADS) {
        int hin = idx / NHID, o = idx % NHID;
        w2t[idx] = W2[k * (NHID * NHID) + o * NHID + hin];
        w3t[idx] = W3[k * (NHID * NHID) + o * NHID + hin];
    }
    if (tid < 2 * NHID) {
        // W4[k, o, hin]: row o=0 is ws, o=1 is wt, both contiguous
        float v = W4[k * (2 * NHID) + tid];
        if (tid < NHID) w4sv[tid] = v; else w4tv[tid - NHID] = v;
    }
    if (tid < NHID) {
        b1s[tid] = b1[k * NHID + tid];
        b2s[tid] = b2[k * NHID + tid];
        b3s[tid] = b3[k * NHID + tid];
    }
    if (tid < 2) b4s[tid] = b4[k * 2 + tid];
    __syncthreads();

    u64 A0[NP], A1[NP], H0[NP], H1[NP];
    const float* x0p = &xs[tid * XPITCH];
    const float* x1p = &xs[(tid + THREADS) * XPITCH];
    const u64* b1p = (const u64*)b1s;
    const u64* b2p = (const u64*)b2s;
    const u64* b3p = (const u64*)b3s;

    // ---- layer 1 (causal: columns 0..k) ----
    #pragma unroll
    for (int o = 0; o < NP; o++) { A0[o] = b1p[o]; A1[o] = b1p[o]; }
    for (int j = 0; j <= k; j++) {
        float xv0 = x0p[j];
        float xv1 = x1p[j];
        u64 v0 = pack2(xv0, xv0);
        u64 v1 = pack2(xv1, xv1);
        const float* wrow = &w1t[j * NHID];
        #pragma unroll
        for (int q = 0; q < NP / 2; q++) {
            u64 w0, w1;
            lds128_pair(wrow + 4 * q, w0, w1);
            A0[2 * q]     = fma2(w0, v0, A0[2 * q]);
            A1[2 * q]     = fma2(w0, v1, A1[2 * q]);
            A0[2 * q + 1] = fma2(w1, v0, A0[2 * q + 1]);
            A1[2 * q + 1] = fma2(w1, v1, A1[2 * q + 1]);
        }
    }
    #pragma unroll
    for (int o = 0; o < NP; o++) { H0[o] = lrelu2(A0[o]); H1[o] = lrelu2(A1[o]); }

    // ---- layer 2 ----
    #pragma unroll
    for (int o = 0; o < NP; o++) { A0[o] = b2p[o]; A1[o] = b2p[o]; }
    #pragma unroll
    for (int hp = 0; hp < NP; hp++) {
        float h0lo, h0hi, h1lo, h1hi;
        unpack2(h0lo, h0hi, H0[hp]);
        unpack2(h1lo, h1hi, H1[hp]);
        u64 va0 = pack2(h0lo, h0lo), vb0 = pack2(h0hi, h0hi);
        u64 va1 = pack2(h1lo, h1lo), vb1 = pack2(h1hi, h1hi);
        const float* rowa = &w2t[(2 * hp) * NHID];
        const float* rowb = &w2t[(2 * hp + 1) * NHID];
        #pragma unroll
        for (int q = 0; q < NP / 2; q++) {
            u64 wa0, wa1, wb0, wb1;
            lds128_pair(rowa + 4 * q, wa0, wa1);
            lds128_pair(rowb + 4 * q, wb0, wb1);
            A0[2 * q]     = fma2(wa0, va0, A0[2 * q]);
            A1[2 * q]     = fma2(wa0, va1, A1[2 * q]);
            A0[2 * q + 1] = fma2(wa1, va0, A0[2 * q + 1]);
            A1[2 * q + 1] = fma2(wa1, va1, A1[2 * q + 1]);
            A0[2 * q]     = fma2(wb0, vb0, A0[2 * q]);
            A1[2 * q]     = fma2(wb0, vb1, A1[2 * q]);
            A0[2 * q + 1] = fma2(wb1, vb0, A0[2 * q + 1]);
            A1[2 * q + 1] = fma2(wb1, vb1, A1[2 * q + 1]);
        }
    }
    #pragma unroll
    for (int o = 0; o < NP; o++) { H0[o] = lrelu2(A0[o]); H1[o] = lrelu2(A1[o]); }

    // ---- layer 3 ----
    #pragma unroll
    for (int o = 0; o < NP; o++) { A0[o] = b3p[o]; A1[o] = b3p[o]; }
    #pragma unroll
    for (int hp = 0; hp < NP; hp++) {
        float h0lo, h0hi, h1lo, h1hi;
        unpack2(h0lo, h0hi, H0[hp]);
        unpack2(h1lo, h1hi, H1[hp]);
        u64 va0 = pack2(h0lo, h0lo), vb0 = pack2(h0hi, h0hi);
        u64 va1 = pack2(h1lo, h1lo), vb1 = pack2(h1hi, h1hi);
        const float* rowa = &w3t[(2 * hp) * NHID];
        const float* rowb = &w3t[(2 * hp + 1) * NHID];
        #pragma unroll
        for (int q = 0; q < NP / 2; q++) {
            u64 wa0, wa1, wb0, wb1;
            lds128_pair(rowa + 4 * q, wa0, wa1);
            lds128_pair(rowb + 4 * q, wb0, wb1);
            A0[2 * q]     = fma2(wa0, va0, A0[2 * q]);
            A1[2 * q]     = fma2(wa0, va1, A1[2 * q]);
            A0[2 * q + 1] = fma2(wa1, va0, A0[2 * q + 1]);
            A1[2 * q + 1] = fma2(wa1, va1, A1[2 * q + 1]);
            A0[2 * q]     = fma2(wb0, vb0, A0[2 * q]);
            A1[2 * q]     = fma2(wb0, vb1, A1[2 * q]);
            A0[2 * q + 1] = fma2(wb1, vb0, A0[2 * q + 1]);
            A1[2 * q + 1] = fma2(wb1, vb1, A1[2 * q + 1]);
        }
    }
    #pragma unroll
    for (int o = 0; o < NP; o++) { H0[o] = lrelu2(A0[o]); H1[o] = lrelu2(A1[o]); }

    // ---- layer 4: packed dot products (lanes = even/odd partial sums) ----
    const u64* wsp = (const u64*)w4sv;
    const u64* wtp = (const u64*)w4tv;
    u64 sa0 = 0, ta0 = 0, sa1 = 0, ta1 = 0;
    #pragma unroll
    for (int hp = 0; hp < NP; hp++) {
        u64 ws = wsp[hp], wt = wtp[hp];
        sa0 = fma2(ws, H0[hp], sa0);
        ta0 = fma2(wt, H0[hp], ta0);
        sa1 = fma2(ws, H1[hp], sa1);
        ta1 = fma2(wt, H1[hp], ta1);
    }
    float e0, o0, e1, o1;
    unpack2(e0, o0, sa0); float s0 = b4s[0] + e0 + o0;
    unpack2(e0, o0, ta0); float t0 = b4s[1] + e0 + o0;
    unpack2(e1, o1, sa1); float s1 = b4s[0] + e1 + o1;
    unpack2(e1, o1, ta1); float t1 = b4s[1] + e1 + o1;

    // ---- epilogue: z[:, 30-k] = x[:,k+1]*exp(s)+t ; logdet += s ----
    const int col  = 30 - k;
    const int row0 = tile + tid;
    const int row1 = row0 + THREADS;
    z[row0 * 32 + col] = x0p[k + 1] * expf(s0) + t0;
    z[row1 * 32 + col] = x1p[k + 1] * expf(s1) + t1;
    atomicAdd(&ld[row0], s0);
    atomicAdd(&ld[row1], s1);
}

extern "C" void kernel_launch(void* const* d_in, const int* in_sizes, int n_in,
                              void* d_out, int out_size) {
    const float* x  = (const float*)d_in[0];
    const float* p0 = (const float*)d_in[1];
    const float* W1 = (const float*)d_in[2];
    const float* b1 = (const float*)d_in[3];
    const float* W2 = (const float*)d_in[4];
    const float* b2 = (const float*)d_in[5];
    const float* W3 = (const float*)d_in[6];
    const float* b3 = (const float*)d_in[7];
    const float* W4 = (const float*)d_in[8];
    const float* b4 = (const float*)d_in[9];

    const int B = in_sizes[0] / 32;          // 65536
    float* z  = (float*)d_out;               // B*32
    float* ld = z + (size_t)B * 32;          // B

    slowmaf_init_kernel<<<(B + 255) / 256, 256>>>(x, p0, z, ld, B);

    dim3 grid(B / ROWS_PER_CTA, 31);
    slowmaf_main_kernel<<<grid, THREADS>>>(x, W1, b1, W2, b2, W3, b3, W4, b4, z, ld);
}

// round 6
// speedup vs baseline: 1.3518x; 1.0553x over previous
#include <cuda_runtime.h>
#include <math.h>

// SlowMAF via warp-level bf16 mma.sync (m16n8k8) with 3-term hi/lo precision split.
// 31 stacked MLPs (32->24->24->24->2, LeakyReLU 0.2);
// z[:, 31-i] = x[:,i]*exp(s_i)+t_i, log_det = sum_i s_i.
// Inputs (metadata order): x, p0, W1, b1, W2, b2, W3, b3, W4, b4
// Output: [ z (B*32 f32), log_det (B f32) ]

#define BATCH 65536
#define NK 31
#define THREADS 128
#define ROWS_CTA 128      // 4 warps x 2 mtiles x 16 rows
#define MT_PER_WARP 2
#define XP 20             // u32 pitch for xs_hi/xs_lo (conflict-free: 20q mod 32 distinct)

typedef unsigned int u32;

__device__ float g_scr[(size_t)NK * BATCH];   // s values, [k][row]

__device__ __forceinline__ void mma8(float d[4], u32 a0, u32 a1, u32 b) {
    asm("mma.sync.aligned.m16n8k8.row.col.f32.bf16.bf16.f32 "
        "{%0,%1,%2,%3}, {%4,%5}, {%6}, {%0,%1,%2,%3};"
        : "+f"(d[0]), "+f"(d[1]), "+f"(d[2]), "+f"(d[3])
        : "r"(a0), "r"(a1), "r"(b));
}

// Split an f32 pair (v0=even col, v1=odd col) into packed bf16x2 hi and lo parts.
// hi = truncation to bf16 (exact top-16 bits, packed via PRMT);
// lo = round-to-nearest bf16 of the remainder.
__device__ __forceinline__ void split_pair(float v0, float v1, u32& hi, u32& lo) {
    u32 b0 = __float_as_uint(v0), b1 = __float_as_uint(v1);
    asm("prmt.b32 %0, %1, %2, 0x7632;" : "=r"(hi) : "r"(b0), "r"(b1));
    float l0 = v0 - __uint_as_float(b0 & 0xFFFF0000u);
    float l1 = v1 - __uint_as_float(b1 & 0xFFFF0000u);
    asm("cvt.rn.bf16x2.f32 %0, %1, %2;" : "=r"(lo) : "f"(l1), "f"(l0));
}

__device__ __forceinline__ float lrelu(float v) { return fmaxf(v, 0.2f * v); }

// One 24-in -> 24-out (3 n-tiles) layer step; C = K/8 chunks.
// Passes: (Ahi x Whi) + (Alo x Whi) + (Ahi x Wlo).
template<int C>
__device__ __forceinline__ void run_layer(const u32* ws, const float* bs, int lw, int cq,
                                          const u32 Ah[][2], const u32 Al[][2],
                                          float D[3][4]) {
    #pragma unroll
    for (int nt = 0; nt < 3; nt++) {
        float q0 = bs[nt * 8 + cq * 2], q1 = bs[nt * 8 + cq * 2 + 1];
        D[nt][0] = q0; D[nt][1] = q1; D[nt][2] = q0; D[nt][3] = q1;
    }
    #pragma unroll
    for (int c = 0; c < C; c++) {
        u32 bh[3];
        #pragma unroll
        for (int nt = 0; nt < 3; nt++) bh[nt] = ws[((nt * 2) * C + c) * 32 + lw];
        #pragma unroll
        for (int nt = 0; nt < 3; nt++) mma8(D[nt], Ah[c][0], Ah[c][1], bh[nt]);
        #pragma unroll
        for (int nt = 0; nt < 3; nt++) mma8(D[nt], Al[c][0], Al[c][1], bh[nt]);
        #pragma unroll
        for (int nt = 0; nt < 3; nt++) {
            u32 bl = ws[((nt * 2 + 1) * C + c) * 32 + lw];
            mma8(D[nt], Ah[c][0], Ah[c][1], bl);
        }
    }
}

__device__ __forceinline__ void make_frags(const float D[3][4], u32 Ah[3][2], u32 Al[3][2]) {
    #pragma unroll
    for (int nt = 0; nt < 3; nt++) {
        split_pair(lrelu(D[nt][0]), lrelu(D[nt][1]), Ah[nt][0], Al[nt][0]);
        split_pair(lrelu(D[nt][2]), lrelu(D[nt][3]), Ah[nt][1], Al[nt][1]);
    }
}

__global__ __launch_bounds__(THREADS, 6) void slowmaf_hmma_kernel(
    const float* __restrict__ x,
    const float* __restrict__ W1, const float* __restrict__ b1,
    const float* __restrict__ W2, const float* __restrict__ b2,
    const float* __restrict__ W3, const float* __restrict__ b3,
    const float* __restrict__ W4, const float* __restrict__ b4,
    float* __restrict__ z)
{
    __shared__ u32 xs_hi[ROWS_CTA * XP];
    __shared__ u32 xs_lo[ROWS_CTA * XP];
    __shared__ u32 w1s[3 * 2 * 4 * 32];   // [nt][part][c][kk*8+n]
    __shared__ u32 w2s[3 * 2 * 3 * 32];
    __shared__ u32 w3s[3 * 2 * 3 * 32];
    __shared__ u32 w4s[2 * 3 * 32];       // [part][c][kk*8+n], single n-tile
    __shared__ float b1s[24], b2s[24], b3s[24], b4s[8];

    const int kidx = blockIdx.y;                 // 0..30 (torch layer i = kidx+1)
    const int tile = blockIdx.x * ROWS_CTA;
    const int tid  = threadIdx.x;

    // ---- stage x: split into bf16 hi/lo pairs ----
    for (int p = tid; p < ROWS_CTA * 16; p += THREADS) {
        int r = p >> 4, cp = p & 15;
        float2 xv = ((const float2*)x)[((size_t)(tile + r) << 4) + cp];
        u32 hi, lo; split_pair(xv.x, xv.y, hi, lo);
        xs_hi[r * XP + cp] = hi;
        xs_lo[r * XP + cp] = lo;
    }
    // ---- stage weights in B-fragment order, hi/lo split ----
    {
        const float* Wk = W1 + (size_t)kidx * (24 * 32);
        for (int e = tid; e < 3 * 4 * 32; e += THREADS) {
            int nt = e >> 7; int rem = e & 127;
            int c = rem >> 5; int kk = (rem >> 3) & 3; int n = rem & 7;
            int k0 = c * 8 + kk * 2, ng = nt * 8 + n;
            float w0 = Wk[ng * 32 + k0];
            float w1v = Wk[ng * 32 + k0 + 1];
            u32 hi, lo; split_pair(w0, w1v, hi, lo);
            int off = ((nt * 2) * 4 + c) * 32 + kk * 8 + n;
            w1s[off] = hi;
            w1s[off + 4 * 32] = lo;
        }
    }
    {
        const float* Wk2 = W2 + (size_t)kidx * (24 * 24);
        const float* Wk3 = W3 + (size_t)kidx * (24 * 24);
        for (int e = tid; e < 3 * 3 * 32; e += THREADS) {
            int nt = e / 96; int rem = e % 96;
            int c = rem >> 5; int kk = (rem >> 3) & 3; int n = rem & 7;
            int k0 = c * 8 + kk * 2, ng = nt * 8 + n;
            int off = ((nt * 2) * 3 + c) * 32 + kk * 8 + n;
            u32 hi, lo;
            split_pair(Wk2[ng * 24 + k0], Wk2[ng * 24 + k0 + 1], hi, lo);
            w2s[off] = hi; w2s[off + 3 * 32] = lo;
            split_pair(Wk3[ng * 24 + k0], Wk3[ng * 24 + k0 + 1], hi, lo);
            w3s[off] = hi; w3s[off + 3 * 32] = lo;
        }
    }
    {
        const float* Wk4 = W4 + (size_t)kidx * (2 * 24);
        for (int e = tid; e < 3 * 32; e += THREADS) {
            int c = e >> 5; int kk = (e >> 3) & 3; int n = e & 7;
            int k0 = c * 8 + kk * 2;
            float w0 = (n < 2) ? Wk4[n * 24 + k0] : 0.0f;
            float w1v = (n < 2) ? Wk4[n * 24 + k0 + 1] : 0.0f;
            u32 hi, lo; split_pair(w0, w1v, hi, lo);
            int off = c * 32 + kk * 8 + n;
            w4s[off] = hi;
            w4s[off + 3 * 32] = lo;
        }
    }
    if (tid < 24) {
        b1s[tid] = b1[kidx * 24 + tid];
        b2s[tid] = b2[kidx * 24 + tid];
        b3s[tid] = b3[kidx * 24 + tid];
    }
    if (tid < 8) b4s[tid] = (tid < 2) ? b4[kidx * 2 + tid] : 0.0f;
    __syncthreads();

    const int warp = tid >> 5, lane = tid & 31;
    const int qr = lane >> 2;        // row-in-8 (also B-frag n)
    const int cq = lane & 3;         // colpair  (also B-frag kk)
    const int lw = cq * 8 + qr;      // B-fragment lane entry

    #pragma unroll
    for (int mt = 0; mt < MT_PER_WARP; mt++) {
        const int rb = warp * (MT_PER_WARP * 16) + mt * 16;
        const int r0 = rb + qr, r1 = r0 + 8;

        // layer-1 A fragments from pre-split x
        u32 A1h[4][2], A1l[4][2];
        #pragma unroll
        for (int c = 0; c < 4; c++) {
            int cp = c * 4 + cq;
            A1h[c][0] = xs_hi[r0 * XP + cp]; A1h[c][1] = xs_hi[r1 * XP + cp];
            A1l[c][0] = xs_lo[r0 * XP + cp]; A1l[c][1] = xs_lo[r1 * XP + cp];
        }

        float D[3][4];
        u32 Ah[3][2], Al[3][2];
        run_layer<4>(w1s, b1s, lw, cq, A1h, A1l, D);   // layer 1 (K=32)
        make_frags(D, Ah, Al);
        run_layer<3>(w2s, b2s, lw, cq, Ah, Al, D);     // layer 2
        make_frags(D, Ah, Al);
        run_layer<3>(w3s, b3s, lw, cq, Ah, Al, D);     // layer 3
        make_frags(D, Ah, Al);

        // layer 4: single n-tile (cols: 0=s, 1=t, 2..7 zero-padded)
        float E[4];
        {
            float q0 = b4s[cq * 2], q1 = b4s[cq * 2 + 1];
            E[0] = q0; E[1] = q1; E[2] = q0; E[3] = q1;
        }
        #pragma unroll
        for (int c = 0; c < 3; c++) {
            u32 bh = w4s[c * 32 + lw];
            mma8(E, Ah[c][0], Ah[c][1], bh);
            mma8(E, Al[c][0], Al[c][1], bh);
            u32 bl = w4s[(3 + c) * 32 + lw];
            mma8(E, Ah[c][0], Ah[c][1], bl);
        }

        // epilogue: only lanes holding cols (0,1)
        if (cq == 0) {
            const int kc = kidx + 1, cp = kc >> 1, odd = kc & 1;
            #pragma unroll
            for (int half = 0; half < 2; half++) {
                int r = half ? r1 : r0;
                float s = E[half * 2], t = E[half * 2 + 1];
                u32 hb = xs_hi[r * XP + cp], lb = xs_lo[r * XP + cp];
                u32 hbits = odd ? (hb & 0xFFFF0000u) : (hb << 16);
                u32 lbits = odd ? (lb & 0xFFFF0000u) : (lb << 16);
                float xv = __uint_as_float(hbits) + __uint_as_float(lbits);
                int grow = tile + r;
                z[grow * 32 + (30 - kidx)] = xv * expf(s) + t;
                g_scr[(size_t)kidx * BATCH + grow] = s;
            }
        }
    }
}

__global__ void slowmaf_finalize_kernel(const float* __restrict__ x,
                                        const float* __restrict__ p0,
                                        float* __restrict__ z,
                                        float* __restrict__ ld)
{
    int row = blockIdx.x * blockDim.x + threadIdx.x;
    float s0 = p0[0];
    float acc = s0;
    #pragma unroll 1
    for (int k = 0; k < NK; k++) acc += g_scr[(size_t)k * BATCH + row];
    ld[row] = acc;
    z[row * 32 + 31] = x[row * 32] * expf(s0) + p0[1];   // order[0] = 31
}

extern "C" void kernel_launch(void* const* d_in, const int* in_sizes, int n_in,
                              void* d_out, int out_size) {
    const float* x  = (const float*)d_in[0];
    const float* p0 = (const float*)d_in[1];
    const float* W1 = (const float*)d_in[2];
    const float* b1 = (const float*)d_in[3];
    const float* W2 = (const float*)d_in[4];
    const float* b2 = (const float*)d_in[5];
    const float* W3 = (const float*)d_in[6];
    const float* b3 = (const float*)d_in[7];
    const float* W4 = (const float*)d_in[8];
    const float* b4 = (const float*)d_in[9];

    float* z  = (float*)d_out;                 // B*32
    float* ld = z + (size_t)BATCH * 32;        // B

    dim3 grid(BATCH / ROWS_CTA, NK);
    slowmaf_hmma_kernel<<<grid, THREADS>>>(x, W1, b1, W2, b2, W3, b3, W4, b4, z);
    slowmaf_finalize_kernel<<<BATCH / 256, 256>>>(x, p0, z, ld);
}

// round 7
// speedup vs baseline: 1.6270x; 1.2036x over previous
#include <cuda_runtime.h>
#include <math.h>

// SlowMAF via warp-level bf16 mma.sync (m16n8k8), 3-term hi/lo split.
// Round 7: weights pre-split once into device scratch (prepass kernel),
// x pre-split into fragment-ordered hi/lo arrays (coalesced LDG.128 A-frags),
// no xs smem, logdet via atomicAdd (no finalize/scratch reduce).
// Inputs (metadata order): x, p0, W1, b1, W2, b2, W3, b3, W4, b4
// Output: [ z (B*32 f32), log_det (B f32) ]

#define BATCH 65536
#define NK 31
#define THREADS 128
#define ROWS_CTA 128      // 4 warps x 2 mtiles x 16 rows
#define MT_PER_WARP 2
#define WBLOB 2192        // u32 per k: w1 768 | w2 576 | w3 576 | w4 192 | biases 80

typedef unsigned int u32;

__device__ u32 g_wblob[NK * WBLOB];
__device__ u32 g_xhi[(size_t)BATCH * 16];
__device__ u32 g_xlo[(size_t)BATCH * 16];

__device__ __forceinline__ void mma8(float d[4], u32 a0, u32 a1, u32 b) {
    asm("mma.sync.aligned.m16n8k8.row.col.f32.bf16.bf16.f32 "
        "{%0,%1,%2,%3}, {%4,%5}, {%6}, {%0,%1,%2,%3};"
        : "+f"(d[0]), "+f"(d[1]), "+f"(d[2]), "+f"(d[3])
        : "r"(a0), "r"(a1), "r"(b));
}

// Split f32 pair (v0=even, v1=odd) into packed bf16x2 hi (truncate) + lo (rn of remainder).
__device__ __forceinline__ void split_pair(float v0, float v1, u32& hi, u32& lo) {
    u32 b0 = __float_as_uint(v0), b1 = __float_as_uint(v1);
    asm("prmt.b32 %0, %1, %2, 0x7632;" : "=r"(hi) : "r"(b0), "r"(b1));
    float l0 = v0 - __uint_as_float(b0 & 0xFFFF0000u);
    float l1 = v1 - __uint_as_float(b1 & 0xFFFF0000u);
    asm("cvt.rn.bf16x2.f32 %0, %1, %2;" : "=r"(lo) : "f"(l1), "f"(l0));
}

__device__ __forceinline__ float lrelu(float v) { return fmaxf(v, 0.2f * v); }

template<int C>
__device__ __forceinline__ void run_layer(const u32* ws, const float* bs, int lw, int cq,
                                          const u32 Ah[][2], const u32 Al[][2],
                                          float D[3][4]) {
    #pragma unroll
    for (int nt = 0; nt < 3; nt++) {
        float q0 = bs[nt * 8 + cq * 2], q1 = bs[nt * 8 + cq * 2 + 1];
        D[nt][0] = q0; D[nt][1] = q1; D[nt][2] = q0; D[nt][3] = q1;
    }
    #pragma unroll
    for (int c = 0; c < C; c++) {
        u32 bh[3];
        #pragma unroll
        for (int nt = 0; nt < 3; nt++) bh[nt] = ws[((nt * 2) * C + c) * 32 + lw];
        #pragma unroll
        for (int nt = 0; nt < 3; nt++) mma8(D[nt], Ah[c][0], Ah[c][1], bh[nt]);
        #pragma unroll
        for (int nt = 0; nt < 3; nt++) mma8(D[nt], Al[c][0], Al[c][1], bh[nt]);
        #pragma unroll
        for (int nt = 0; nt < 3; nt++) {
            u32 bl = ws[((nt * 2 + 1) * C + c) * 32 + lw];
            mma8(D[nt], Ah[c][0], Ah[c][1], bl);
        }
    }
}

__device__ __forceinline__ void make_frags(const float D[3][4], u32 Ah[3][2], u32 Al[3][2]) {
    #pragma unroll
    for (int nt = 0; nt < 3; nt++) {
        split_pair(lrelu(D[nt][0]), lrelu(D[nt][1]), Ah[nt][0], Al[nt][0]);
        split_pair(lrelu(D[nt][2]), lrelu(D[nt][3]), Ah[nt][1], Al[nt][1]);
    }
}

// ---- prepass: split + fragment-order all weights for one k into g_wblob ----
__global__ void slowmaf_wprep_kernel(
    const float* __restrict__ W1, const float* __restrict__ b1,
    const float* __restrict__ W2, const float* __restrict__ b2,
    const float* __restrict__ W3, const float* __restrict__ b3,
    const float* __restrict__ W4, const float* __restrict__ b4)
{
    const int k = blockIdx.x;
    const int tid = threadIdx.x;
    u32* blob = g_wblob + k * WBLOB;

    {
        const float* Wk = W1 + (size_t)k * (24 * 32);
        for (int e = tid; e < 3 * 4 * 32; e += THREADS) {
            int nt = e >> 7; int rem = e & 127;
            int c = rem >> 5; int kk = (rem >> 3) & 3; int n = rem & 7;
            int k0 = c * 8 + kk * 2, ng = nt * 8 + n;
            u32 hi, lo; split_pair(Wk[ng * 32 + k0], Wk[ng * 32 + k0 + 1], hi, lo);
            int off = ((nt * 2) * 4 + c) * 32 + kk * 8 + n;
            blob[off] = hi;
            blob[off + 4 * 32] = lo;
        }
    }
    {
        const float* Wk2 = W2 + (size_t)k * (24 * 24);
        const float* Wk3 = W3 + (size_t)k * (24 * 24);
        for (int e = tid; e < 3 * 3 * 32; e += THREADS) {
            int nt = e / 96; int rem = e % 96;
            int c = rem >> 5; int kk = (rem >> 3) & 3; int n = rem & 7;
            int k0 = c * 8 + kk * 2, ng = nt * 8 + n;
            int off = ((nt * 2) * 3 + c) * 32 + kk * 8 + n;
            u32 hi, lo;
            split_pair(Wk2[ng * 24 + k0], Wk2[ng * 24 + k0 + 1], hi, lo);
            blob[768 + off] = hi; blob[768 + off + 96] = lo;
            split_pair(Wk3[ng * 24 + k0], Wk3[ng * 24 + k0 + 1], hi, lo);
            blob[1344 + off] = hi; blob[1344 + off + 96] = lo;
        }
    }
    {
        const float* Wk4 = W4 + (size_t)k * (2 * 24);
        for (int e = tid; e < 3 * 32; e += THREADS) {
            int c = e >> 5; int kk = (e >> 3) & 3; int n = e & 7;
            int k0 = c * 8 + kk * 2;
            float w0 = (n < 2) ? Wk4[n * 24 + k0] : 0.0f;
            float w1v = (n < 2) ? Wk4[n * 24 + k0 + 1] : 0.0f;
            u32 hi, lo; split_pair(w0, w1v, hi, lo);
            blob[1920 + c * 32 + kk * 8 + n] = hi;
            blob[1920 + c * 32 + kk * 8 + n + 96] = lo;
        }
    }
    float* fb = (float*)(blob + 2112);
    if (tid < 24) {
        fb[tid]      = b1[k * 24 + tid];
        fb[24 + tid] = b2[k * 24 + tid];
        fb[48 + tid] = b3[k * 24 + tid];
    }
    if (tid < 8) fb[72 + tid] = (tid < 2) ? b4[k * 2 + tid] : 0.0f;
}

// ---- prepass: split x into hi/lo, fragment-ordered within each row ----
// dst index: row*16 + cq*4 + c  where source pair cp = c*4 + cq
__global__ void slowmaf_xsplit_kernel(const float* __restrict__ x) {
    int p = blockIdx.x * blockDim.x + threadIdx.x;   // < BATCH*16
    int row = p >> 4, cp = p & 15;
    float2 xv = ((const float2*)x)[p];
    u32 hi, lo; split_pair(xv.x, xv.y, hi, lo);
    int dst = (row << 4) + ((cp & 3) << 2) + (cp >> 2);
    g_xhi[dst] = hi;
    g_xlo[dst] = lo;
}

__global__ void slowmaf_init_kernel(const float* __restrict__ x,
                                    const float* __restrict__ p0,
                                    float* __restrict__ z,
                                    float* __restrict__ ld) {
    int row = blockIdx.x * blockDim.x + threadIdx.x;
    float s0 = p0[0];
    z[row * 32 + 31] = x[row * 32] * expf(s0) + p0[1];   // order[0] = 31
    ld[row] = s0;
}

__global__ __launch_bounds__(THREADS, 6) void slowmaf_hmma_kernel(
    const float* __restrict__ x, float* __restrict__ z, float* __restrict__ ld)
{
    __shared__ __align__(16) u32 wsm[WBLOB];

    const int kidx = blockIdx.y;                 // 0..30
    const int tile = blockIdx.x * ROWS_CTA;
    const int tid  = threadIdx.x;

    // copy pre-split weight blob (548 uint4)
    {
        const uint4* src = (const uint4*)(g_wblob + kidx * WBLOB);
        uint4* dst = (uint4*)wsm;
        #pragma unroll
        for (int i = 0; i < 5; i++) {
            int e = i * THREADS + tid;
            if (e < WBLOB / 4) dst[e] = src[e];
        }
    }
    __syncthreads();

    const u32* w1s = wsm;
    const u32* w2s = wsm + 768;
    const u32* w3s = wsm + 1344;
    const u32* w4s = wsm + 1920;
    const float* fb  = (const float*)(wsm + 2112);
    const float* b1s = fb, *b2s = fb + 24, *b3s = fb + 48, *b4s = fb + 72;

    const int warp = tid >> 5, lane = tid & 31;
    const int qr = lane >> 2;        // row-in-8 (B-frag n)
    const int cq = lane & 3;         // colpair  (B-frag kk)
    const int lw = cq * 8 + qr;

    #pragma unroll
    for (int mt = 0; mt < MT_PER_WARP; mt++) {
        const int rb = warp * (MT_PER_WARP * 16) + mt * 16;
        const int r0 = rb + qr, r1 = r0 + 8;
        const size_t g0 = ((size_t)(tile + r0) << 4) + (cq << 2);
        const size_t g1 = ((size_t)(tile + r1) << 4) + (cq << 2);

        u32 A1h[4][2], A1l[4][2];
        {
            uint4 H0 = *(const uint4*)(g_xhi + g0);
            uint4 H1 = *(const uint4*)(g_xhi + g1);
            uint4 L0 = *(const uint4*)(g_xlo + g0);
            uint4 L1 = *(const uint4*)(g_xlo + g1);
            A1h[0][0] = H0.x; A1h[1][0] = H0.y; A1h[2][0] = H0.z; A1h[3][0] = H0.w;
            A1h[0][1] = H1.x; A1h[1][1] = H1.y; A1h[2][1] = H1.z; A1h[3][1] = H1.w;
            A1l[0][0] = L0.x; A1l[1][0] = L0.y; A1l[2][0] = L0.z; A1l[3][0] = L0.w;
            A1l[0][1] = L1.x; A1l[1][1] = L1.y; A1l[2][1] = L1.z; A1l[3][1] = L1.w;
        }

        float D[3][4];
        u32 Ah[3][2], Al[3][2];
        run_layer<4>(w1s, b1s, lw, cq, A1h, A1l, D);   // layer 1 (K=32)
        make_frags(D, Ah, Al);
        run_layer<3>(w2s, b2s, lw, cq, Ah, Al, D);     // layer 2
        make_frags(D, Ah, Al);
        run_layer<3>(w3s, b3s, lw, cq, Ah, Al, D);     // layer 3
        make_frags(D, Ah, Al);

        // layer 4: single n-tile (cols 0=s, 1=t)
        float E[4];
        {
            float q0 = b4s[cq * 2], q1 = b4s[cq * 2 + 1];
            E[0] = q0; E[1] = q1; E[2] = q0; E[3] = q1;
        }
        #pragma unroll
        for (int c = 0; c < 3; c++) {
            u32 bh = w4s[c * 32 + lw];
            mma8(E, Ah[c][0], Ah[c][1], bh);
            mma8(E, Al[c][0], Al[c][1], bh);
            u32 bl = w4s[(3 + c) * 32 + lw];
            mma8(E, Ah[c][0], Ah[c][1], bl);
        }

        if (cq == 0) {
            const int kc = kidx + 1;
            #pragma unroll
            for (int half = 0; half < 2; half++) {
                int grow = tile + (half ? r1 : r0);
                float s = E[half * 2], t = E[half * 2 + 1];
                float xv = x[grow * 32 + kc];
                z[grow * 32 + (30 - kidx)] = xv * expf(s) + t;
                atomicAdd(&ld[grow], s);
            }
        }
    }
}

extern "C" void kernel_launch(void* const* d_in, const int* in_sizes, int n_in,
                              void* d_out, int out_size) {
    const float* x  = (const float*)d_in[0];
    const float* p0 = (const float*)d_in[1];
    const float* W1 = (const float*)d_in[2];
    const float* b1 = (const float*)d_in[3];
    const float* W2 = (const float*)d_in[4];
    const float* b2 = (const float*)d_in[5];
    const float* W3 = (const float*)d_in[6];
    const float* b3 = (const float*)d_in[7];
    const float* W4 = (const float*)d_in[8];
    const float* b4 = (const float*)d_in[9];

    float* z  = (float*)d_out;                 // B*32
    float* ld = z + (size_t)BATCH * 32;        // B

    slowmaf_wprep_kernel<<<NK, THREADS>>>(W1, b1, W2, b2, W3, b3, W4, b4);
    slowmaf_xsplit_kernel<<<BATCH * 16 / 256, 256>>>(x);
    slowmaf_init_kernel<<<BATCH / 256, 256>>>(x, p0, z, ld);

    dim3 grid(BATCH / ROWS_CTA, NK);
    slowmaf_hmma_kernel<<<grid, THREADS>>>(x, z, ld);
}